// round 2
// baseline (speedup 1.0000x reference)
#include <cuda_runtime.h>
#include <math.h>
#include <float.h>
#include <stdint.h>

// Problem dims (fixed by the dataset)
#define B_ROWS 2048
#define N_KEYS 50000
#define D_DIM  256
#define V_DIM  256
#define TOPK   8
#define N_PAD  50048   // 391 * 128, padded key count for GEMM grid

// ---------------------------------------------------------------------------
// Scratch (static __device__ arrays; allocation inside kernel_launch is banned)
// ---------------------------------------------------------------------------
__device__ float g_q[B_ROWS * D_DIM];                   // q = query @ W^T + b -> q_norm (in place)
__device__ float g_kn[(size_t)N_KEYS * D_DIM];          // k_norm = keys / max(||k||, eps)
__device__ float g_sim[(size_t)B_ROWS * N_PAD];         // similarity matrix scratch (~410 MB)
__device__ int   g_topi[B_ROWS * TOPK];                 // top-k indices

// ---------------------------------------------------------------------------
// NT SGEMM: C[m,n] = sum_k A[m,k] * B[n,k]  (+ bias[n] if bias != null)
// A: M x K row-major, B: N x K row-major. BM=BN=128, BK=16, 256 thr, 8x8/thread.
// Serial ascending-k fma accumulation per (m,n) to mirror reference numerics.
// ---------------------------------------------------------------------------
#define BM 128
#define BN 128
#define BK 16

__global__ void __launch_bounds__(256) gemm_nt_kernel(
    const float* __restrict__ A, const float* __restrict__ B,
    float* __restrict__ C, const float* __restrict__ bias,
    int N, int K, int ldc)
{
    __shared__ float As[BK][BM];
    __shared__ float Bs[BK][BN];

    const int tid = threadIdx.x;
    const int tx  = tid & 15;         // 0..15 -> n
    const int ty  = tid >> 4;         // 0..15 -> m
    const int m0  = blockIdx.y * BM;
    const int n0  = blockIdx.x * BN;

    const int lr = tid >> 2;          // 0..63  tile row for loads
    const int lc = (tid & 3) * 4;     // 0,4,8,12 (k offset, float4)

    const float* Aptr = A + (size_t)m0 * K;
    const float* Bptr = B + (size_t)n0 * K;

    float acc[8][8];
#pragma unroll
    for (int i = 0; i < 8; ++i)
#pragma unroll
        for (int j = 0; j < 8; ++j) acc[i][j] = 0.f;

    for (int k0 = 0; k0 < K; k0 += BK) {
        // Load A tile (128x16), transpose into As[k][m]
#pragma unroll
        for (int h = 0; h < 2; ++h) {
            int r = lr + h * 64;
            float4 v = *(const float4*)(Aptr + (size_t)r * K + k0 + lc);
            As[lc + 0][r] = v.x; As[lc + 1][r] = v.y;
            As[lc + 2][r] = v.z; As[lc + 3][r] = v.w;
        }
        // Load B tile (128x16) with row guard, transpose into Bs[k][n]
#pragma unroll
        for (int h = 0; h < 2; ++h) {
            int r = lr + h * 64;
            float4 v = make_float4(0.f, 0.f, 0.f, 0.f);
            if (n0 + r < N) v = *(const float4*)(Bptr + (size_t)r * K + k0 + lc);
            Bs[lc + 0][r] = v.x; Bs[lc + 1][r] = v.y;
            Bs[lc + 2][r] = v.z; Bs[lc + 3][r] = v.w;
        }
        __syncthreads();

#pragma unroll
        for (int kk = 0; kk < BK; ++kk) {
            float ra[8], rb[8];
            *(float4*)&ra[0] = *(const float4*)&As[kk][ty * 8];
            *(float4*)&ra[4] = *(const float4*)&As[kk][ty * 8 + 4];
            *(float4*)&rb[0] = *(const float4*)&Bs[kk][tx * 8];
            *(float4*)&rb[4] = *(const float4*)&Bs[kk][tx * 8 + 4];
#pragma unroll
            for (int i = 0; i < 8; ++i)
#pragma unroll
                for (int j = 0; j < 8; ++j)
                    acc[i][j] = fmaf(ra[i], rb[j], acc[i][j]);
        }
        __syncthreads();
    }

    // Epilogue: optional bias, vectorized stores
    float bi[8];
#pragma unroll
    for (int j = 0; j < 8; ++j) {
        int n = n0 + tx * 8 + j;
        bi[j] = bias ? ((n < N) ? bias[n] : 0.f) : 0.f;
    }
#pragma unroll
    for (int i = 0; i < 8; ++i) {
        int m = m0 + ty * 8 + i;
        float* crow = C + (size_t)m * ldc + n0 + tx * 8;
#pragma unroll
        for (int jv = 0; jv < 8; jv += 4) {
            float4 w;
            w.x = acc[i][jv + 0] + bi[jv + 0];
            w.y = acc[i][jv + 1] + bi[jv + 1];
            w.z = acc[i][jv + 2] + bi[jv + 2];
            w.w = acc[i][jv + 3] + bi[jv + 3];
            *(float4*)(crow + jv) = w;
        }
    }
}

// ---------------------------------------------------------------------------
// Row L2-normalize: dst = src / max(||src||_2, 1e-12), IEEE div + sqrt to
// match the reference's elementwise rounding. One warp per row, D=256.
// src may equal dst.
// ---------------------------------------------------------------------------
__global__ void l2norm_rows_kernel(const float* __restrict__ src,
                                   float* __restrict__ dst, int rows)
{
    int row  = blockIdx.x * 8 + (threadIdx.x >> 5);
    int lane = threadIdx.x & 31;
    if (row >= rows) return;
    const float4* p = (const float4*)(src + (size_t)row * D_DIM);
    float4 v0 = p[lane];
    float4 v1 = p[lane + 32];
    float ss = v0.x * v0.x + v0.y * v0.y + v0.z * v0.z + v0.w * v0.w
             + v1.x * v1.x + v1.y * v1.y + v1.z * v1.z + v1.w * v1.w;
#pragma unroll
    for (int off = 16; off > 0; off >>= 1)
        ss += __shfl_xor_sync(0xffffffffu, ss, off);
    float den = fmaxf(__fsqrt_rn(ss), 1e-12f);
    v0.x = __fdiv_rn(v0.x, den); v0.y = __fdiv_rn(v0.y, den);
    v0.z = __fdiv_rn(v0.z, den); v0.w = __fdiv_rn(v0.w, den);
    v1.x = __fdiv_rn(v1.x, den); v1.y = __fdiv_rn(v1.y, den);
    v1.z = __fdiv_rn(v1.z, den); v1.w = __fdiv_rn(v1.w, den);
    float4* q = (float4*)(dst + (size_t)row * D_DIM);
    q[lane]      = v0;
    q[lane + 32] = v1;
}

// ---------------------------------------------------------------------------
// Per-row top-8. One block (256 threads) per query row. Descending scores,
// ties broken by smaller index (matches jax.lax.top_k stability).
// ---------------------------------------------------------------------------
__device__ __forceinline__ bool tk_better(float s1, int i1, float s2, int i2)
{
    return (s1 > s2) || (s1 == s2 && i1 < i2);
}

__global__ void __launch_bounds__(256) topk_kernel(
    const float* __restrict__ sim, float* __restrict__ out_scores, int* __restrict__ topi)
{
    __shared__ float ss[256 * TOPK];
    __shared__ int   si[256 * TOPK];
    __shared__ float rs[256];
    __shared__ int   rk[256];
    __shared__ int   rp[256];

    const int r   = blockIdx.x;
    const int tid = threadIdx.x;
    const float* row = sim + (size_t)r * N_PAD;

    float ls[TOPK]; int li[TOPK];
#pragma unroll
    for (int j = 0; j < TOPK; ++j) { ls[j] = -FLT_MAX; li[j] = 0x7fffffff; }

    for (int n = tid; n < N_KEYS; n += 256) {
        float s = row[n];
        if (tk_better(s, n, ls[TOPK - 1], li[TOPK - 1])) {
            ls[TOPK - 1] = s; li[TOPK - 1] = n;
#pragma unroll
            for (int q = TOPK - 1; q > 0; --q) {
                if (tk_better(ls[q], li[q], ls[q - 1], li[q - 1])) {
                    float tf = ls[q]; ls[q] = ls[q - 1]; ls[q - 1] = tf;
                    int   ti = li[q]; li[q] = li[q - 1]; li[q - 1] = ti;
                }
            }
        }
    }
#pragma unroll
    for (int j = 0; j < TOPK; ++j) { ss[tid * TOPK + j] = ls[j]; si[tid * TOPK + j] = li[j]; }
    __syncthreads();

    for (int it = 0; it < TOPK; ++it) {
        float bs = -FLT_MAX; int bk = 0x7fffffff; int bp = -1;
#pragma unroll
        for (int j = 0; j < TOPK; ++j) {
            int p = tid * TOPK + j;
            if (tk_better(ss[p], si[p], bs, bk)) { bs = ss[p]; bk = si[p]; bp = p; }
        }
        rs[tid] = bs; rk[tid] = bk; rp[tid] = bp;
        __syncthreads();
        for (int off = 128; off > 0; off >>= 1) {
            if (tid < off) {
                if (tk_better(rs[tid + off], rk[tid + off], rs[tid], rk[tid])) {
                    rs[tid] = rs[tid + off]; rk[tid] = rk[tid + off]; rp[tid] = rp[tid + off];
                }
            }
            __syncthreads();
        }
        if (tid == 0) {
            out_scores[r * TOPK + it] = rs[0];
            topi[r * TOPK + it]       = rk[0];
            ss[rp[0]] = -FLT_MAX;       // remove winner
        }
        __syncthreads();
    }
}

// ---------------------------------------------------------------------------
// usage passthrough, then gather + usage increment
// ---------------------------------------------------------------------------
__global__ void usage_init_kernel(const float* __restrict__ usage, float* __restrict__ out_usage)
{
    int i = blockIdx.x * blockDim.x + threadIdx.x;
    if (i < N_KEYS) out_usage[i] = usage[i];
}

__global__ void gather_kernel(const float* __restrict__ values, const int* __restrict__ topi,
                              float* __restrict__ out_rv, float* __restrict__ out_usage)
{
    int slot = blockIdx.x;                // 0 .. B_ROWS*TOPK-1
    int idx  = topi[slot];
    if (threadIdx.x == 0) atomicAdd(&out_usage[idx], 1.0f);
    const float4* src = (const float4*)(values + (size_t)idx * V_DIM);
    float4*       dst = (float4*)(out_rv + (size_t)slot * V_DIM);
    dst[threadIdx.x] = src[threadIdx.x];  // 64 threads x float4 = 256 floats
}

// ---------------------------------------------------------------------------
// Launch
// Inputs: 0=query (2048x256), 1=W (256x256), 2=b (256), 3=keys (50000x256),
//         4=values (50000x256), 5=usage (50000), 6=top_k (scalar, ignored=8)
// Output: [retrieved_values | scores | usage_new] float32
// ---------------------------------------------------------------------------
extern "C" void kernel_launch(void* const* d_in, const int* in_sizes, int n_in,
                              void* d_out, int out_size)
{
    const float* query  = (const float*)d_in[0];
    const float* W      = (const float*)d_in[1];
    const float* bias   = (const float*)d_in[2];
    const float* keys   = (const float*)d_in[3];
    const float* values = (const float*)d_in[4];
    const float* usage  = (const float*)d_in[5];

    float* out       = (float*)d_out;
    float* out_rv    = out;                                   // 2048*8*256
    float* out_sc    = out + (size_t)B_ROWS * TOPK * V_DIM;   // 2048*8
    float* out_usage = out_sc + (size_t)B_ROWS * TOPK;        // 50000

    float* q    = nullptr; cudaGetSymbolAddress((void**)&q,    g_q);
    float* kn   = nullptr; cudaGetSymbolAddress((void**)&kn,   g_kn);
    float* sim  = nullptr; cudaGetSymbolAddress((void**)&sim,  g_sim);
    int*   topi = nullptr; cudaGetSymbolAddress((void**)&topi, g_topi);

    // 1) q = query @ W^T + b     (M=2048, N=256, K=256)
    gemm_nt_kernel<<<dim3(D_DIM / BN, B_ROWS / BM), 256>>>(
        query, W, q, bias, D_DIM, D_DIM, D_DIM);

    // 2) q_norm = q / max(||q||, eps)  (in place, IEEE div)
    l2norm_rows_kernel<<<B_ROWS / 8, 256>>>(q, q, B_ROWS);

    // 3) k_norm = keys / max(||k||, eps)  (materialized, IEEE div)
    l2norm_rows_kernel<<<(N_KEYS + 7) / 8, 256>>>(keys, kn, N_KEYS);

    // 4) sim = q_norm @ k_norm^T     (M=2048, N=50000 padded to 50048)
    gemm_nt_kernel<<<dim3(N_PAD / BN, B_ROWS / BM), 256>>>(
        q, kn, sim, nullptr, N_KEYS, D_DIM, N_PAD);

    // 5) top-8 per row -> scores (direct to output) + indices
    topk_kernel<<<B_ROWS, 256>>>(sim, out_sc, topi);

    // 6) usage passthrough, then gather + usage increments
    usage_init_kernel<<<(N_KEYS + 255) / 256, 256>>>(usage, out_usage);
    gather_kernel<<<B_ROWS * TOPK, 64>>>(values, topi, out_rv, out_usage);
}

// round 3
// speedup vs baseline: 1.0022x; 1.0022x over previous
#include <cuda_runtime.h>
#include <math.h>
#include <float.h>
#include <stdint.h>

// Problem dims (fixed by the dataset)
#define B_ROWS 2048
#define N_KEYS 50000
#define D_DIM  256
#define V_DIM  256
#define TOPK   8
#define N_PAD  50048   // 391 * 128, padded key count for GEMM grid

// ---------------------------------------------------------------------------
// Scratch (static __device__ arrays; allocation inside kernel_launch is banned)
// ---------------------------------------------------------------------------
__device__ float g_q[B_ROWS * D_DIM];                   // q = query @ W^T + b -> q_norm (in place)
__device__ float g_kn[(size_t)N_KEYS * D_DIM];          // k_norm = keys / max(||k||, eps)
__device__ float g_sim[(size_t)B_ROWS * N_PAD];         // similarity matrix scratch (~410 MB)
__device__ int   g_topi[B_ROWS * TOPK];                 // top-k indices

// ---------------------------------------------------------------------------
// Packed fp32x2 helpers (Blackwell FFMA2; each lane is an exact IEEE fma.rn,
// so numerics are bitwise identical to the scalar fmaf chain).
// ---------------------------------------------------------------------------
__device__ __forceinline__ unsigned long long pack2(float x, float y)
{
    unsigned long long r;
    asm("mov.b64 %0, {%1, %2};" : "=l"(r) : "f"(x), "f"(y));
    return r;
}
__device__ __forceinline__ void unpack2(unsigned long long v, float& x, float& y)
{
    asm("mov.b64 {%0, %1}, %2;" : "=f"(x), "=f"(y) : "l"(v));
}
__device__ __forceinline__ void ffma2(unsigned long long& d,
                                      unsigned long long a, unsigned long long b)
{
    // d = a * b + d   (two independent fp32 lanes, round-to-nearest)
    asm("fma.rn.f32x2 %0, %1, %2, %0;" : "+l"(d) : "l"(a), "l"(b));
}

// ---------------------------------------------------------------------------
// NT SGEMM: C[m,n] = sum_k A[m,k] * B[n,k]  (+ bias[n] if bias != null)
// A: M x K row-major, B: N x K row-major. BM=BN=128, BK=16, 256 thr.
// 8x8 register tile held as 8x4 packed f32x2 accumulators; k-serial
// ascending accumulation per (m,n) to mirror reference numerics exactly.
// ---------------------------------------------------------------------------
#define BM 128
#define BN 128
#define BK 16

__global__ void __launch_bounds__(256) gemm_nt_kernel(
    const float* __restrict__ A, const float* __restrict__ B,
    float* __restrict__ C, const float* __restrict__ bias,
    int N, int K, int ldc)
{
    __shared__ float As[BK][BM];
    __shared__ float Bs[BK][BN];

    const int tid = threadIdx.x;
    const int tx  = tid & 15;         // 0..15 -> n
    const int ty  = tid >> 4;         // 0..15 -> m
    const int m0  = blockIdx.y * BM;
    const int n0  = blockIdx.x * BN;

    const int lr = tid >> 2;          // 0..63  tile row for loads
    const int lc = (tid & 3) * 4;     // 0,4,8,12 (k offset, float4)

    const float* Aptr = A + (size_t)m0 * K;
    const float* Bptr = B + (size_t)n0 * K;

    unsigned long long acc2[8][4];    // [i][j2] packs columns (2*j2, 2*j2+1)
#pragma unroll
    for (int i = 0; i < 8; ++i)
#pragma unroll
        for (int j = 0; j < 4; ++j) acc2[i][j] = 0ull;   // {0.f, 0.f}

    for (int k0 = 0; k0 < K; k0 += BK) {
        // Load A tile (128x16), transpose into As[k][m]
#pragma unroll
        for (int h = 0; h < 2; ++h) {
            int r = lr + h * 64;
            float4 v = *(const float4*)(Aptr + (size_t)r * K + k0 + lc);
            As[lc + 0][r] = v.x; As[lc + 1][r] = v.y;
            As[lc + 2][r] = v.z; As[lc + 3][r] = v.w;
        }
        // Load B tile (128x16) with row guard, transpose into Bs[k][n]
#pragma unroll
        for (int h = 0; h < 2; ++h) {
            int r = lr + h * 64;
            float4 v = make_float4(0.f, 0.f, 0.f, 0.f);
            if (n0 + r < N) v = *(const float4*)(Bptr + (size_t)r * K + k0 + lc);
            Bs[lc + 0][r] = v.x; Bs[lc + 1][r] = v.y;
            Bs[lc + 2][r] = v.z; Bs[lc + 3][r] = v.w;
        }
        __syncthreads();

#pragma unroll
        for (int kk = 0; kk < BK; ++kk) {
            float ra[8];
            *(float4*)&ra[0] = *(const float4*)&As[kk][ty * 8];
            *(float4*)&ra[4] = *(const float4*)&As[kk][ty * 8 + 4];
            // B pairs are adjacent in shared -> read directly as packed 64-bit
            const ulonglong2* bp = (const ulonglong2*)&Bs[kk][tx * 8];
            ulonglong2 b01 = bp[0];
            ulonglong2 b23 = bp[1];
            unsigned long long rb2[4] = { b01.x, b01.y, b23.x, b23.y };

            unsigned long long ra2[8];
#pragma unroll
            for (int i = 0; i < 8; ++i) ra2[i] = pack2(ra[i], ra[i]);

#pragma unroll
            for (int i = 0; i < 8; ++i)
#pragma unroll
                for (int j = 0; j < 4; ++j)
                    ffma2(acc2[i][j], ra2[i], rb2[j]);
        }
        __syncthreads();
    }

    // Epilogue: optional bias, vectorized stores
    float bi[8];
#pragma unroll
    for (int j = 0; j < 8; ++j) {
        int n = n0 + tx * 8 + j;
        bi[j] = bias ? ((n < N) ? bias[n] : 0.f) : 0.f;
    }
#pragma unroll
    for (int i = 0; i < 8; ++i) {
        int m = m0 + ty * 8 + i;
        float* crow = C + (size_t)m * ldc + n0 + tx * 8;
#pragma unroll
        for (int jv = 0; jv < 2; ++jv) {
            float a0, a1, a2, a3;
            unpack2(acc2[i][jv * 2 + 0], a0, a1);
            unpack2(acc2[i][jv * 2 + 1], a2, a3);
            float4 w;
            w.x = a0 + bi[jv * 4 + 0];
            w.y = a1 + bi[jv * 4 + 1];
            w.z = a2 + bi[jv * 4 + 2];
            w.w = a3 + bi[jv * 4 + 3];
            *(float4*)(crow + jv * 4) = w;
        }
    }
}

// ---------------------------------------------------------------------------
// Row L2-normalize: dst = src / max(||src||_2, 1e-12), IEEE div + sqrt to
// match the reference's elementwise rounding. One warp per row, D=256.
// src may equal dst.
// ---------------------------------------------------------------------------
__global__ void l2norm_rows_kernel(const float* __restrict__ src,
                                   float* __restrict__ dst, int rows)
{
    int row  = blockIdx.x * 8 + (threadIdx.x >> 5);
    int lane = threadIdx.x & 31;
    if (row >= rows) return;
    const float4* p = (const float4*)(src + (size_t)row * D_DIM);
    float4 v0 = p[lane];
    float4 v1 = p[lane + 32];
    float ss = v0.x * v0.x + v0.y * v0.y + v0.z * v0.z + v0.w * v0.w
             + v1.x * v1.x + v1.y * v1.y + v1.z * v1.z + v1.w * v1.w;
#pragma unroll
    for (int off = 16; off > 0; off >>= 1)
        ss += __shfl_xor_sync(0xffffffffu, ss, off);
    float den = fmaxf(__fsqrt_rn(ss), 1e-12f);
    v0.x = __fdiv_rn(v0.x, den); v0.y = __fdiv_rn(v0.y, den);
    v0.z = __fdiv_rn(v0.z, den); v0.w = __fdiv_rn(v0.w, den);
    v1.x = __fdiv_rn(v1.x, den); v1.y = __fdiv_rn(v1.y, den);
    v1.z = __fdiv_rn(v1.z, den); v1.w = __fdiv_rn(v1.w, den);
    float4* q = (float4*)(dst + (size_t)row * D_DIM);
    q[lane]      = v0;
    q[lane + 32] = v1;
}

// ---------------------------------------------------------------------------
// Per-row top-8. One block (256 threads) per query row. Descending scores,
// ties broken by smaller index (matches jax.lax.top_k stability).
// ---------------------------------------------------------------------------
__device__ __forceinline__ bool tk_better(float s1, int i1, float s2, int i2)
{
    return (s1 > s2) || (s1 == s2 && i1 < i2);
}

__global__ void __launch_bounds__(256) topk_kernel(
    const float* __restrict__ sim, float* __restrict__ out_scores, int* __restrict__ topi)
{
    __shared__ float ss[256 * TOPK];
    __shared__ int   si[256 * TOPK];
    __shared__ float rs[256];
    __shared__ int   rk[256];
    __shared__ int   rp[256];

    const int r   = blockIdx.x;
    const int tid = threadIdx.x;
    const float* row = sim + (size_t)r * N_PAD;

    float ls[TOPK]; int li[TOPK];
#pragma unroll
    for (int j = 0; j < TOPK; ++j) { ls[j] = -FLT_MAX; li[j] = 0x7fffffff; }

    for (int n = tid; n < N_KEYS; n += 256) {
        float s = row[n];
        if (tk_better(s, n, ls[TOPK - 1], li[TOPK - 1])) {
            ls[TOPK - 1] = s; li[TOPK - 1] = n;
#pragma unroll
            for (int q = TOPK - 1; q > 0; --q) {
                if (tk_better(ls[q], li[q], ls[q - 1], li[q - 1])) {
                    float tf = ls[q]; ls[q] = ls[q - 1]; ls[q - 1] = tf;
                    int   ti = li[q]; li[q] = li[q - 1]; li[q - 1] = ti;
                }
            }
        }
    }
#pragma unroll
    for (int j = 0; j < TOPK; ++j) { ss[tid * TOPK + j] = ls[j]; si[tid * TOPK + j] = li[j]; }
    __syncthreads();

    for (int it = 0; it < TOPK; ++it) {
        float bs = -FLT_MAX; int bk = 0x7fffffff; int bp = -1;
#pragma unroll
        for (int j = 0; j < TOPK; ++j) {
            int p = tid * TOPK + j;
            if (tk_better(ss[p], si[p], bs, bk)) { bs = ss[p]; bk = si[p]; bp = p; }
        }
        rs[tid] = bs; rk[tid] = bk; rp[tid] = bp;
        __syncthreads();
        for (int off = 128; off > 0; off >>= 1) {
            if (tid < off) {
                if (tk_better(rs[tid + off], rk[tid + off], rs[tid], rk[tid])) {
                    rs[tid] = rs[tid + off]; rk[tid] = rk[tid + off]; rp[tid] = rp[tid + off];
                }
            }
            __syncthreads();
        }
        if (tid == 0) {
            out_scores[r * TOPK + it] = rs[0];
            topi[r * TOPK + it]       = rk[0];
            ss[rp[0]] = -FLT_MAX;       // remove winner
        }
        __syncthreads();
    }
}

// ---------------------------------------------------------------------------
// usage passthrough, then gather + usage increment
// ---------------------------------------------------------------------------
__global__ void usage_init_kernel(const float* __restrict__ usage, float* __restrict__ out_usage)
{
    int i = blockIdx.x * blockDim.x + threadIdx.x;
    if (i < N_KEYS) out_usage[i] = usage[i];
}

__global__ void gather_kernel(const float* __restrict__ values, const int* __restrict__ topi,
                              float* __restrict__ out_rv, float* __restrict__ out_usage)
{
    int slot = blockIdx.x;                // 0 .. B_ROWS*TOPK-1
    int idx  = topi[slot];
    if (threadIdx.x == 0) atomicAdd(&out_usage[idx], 1.0f);
    const float4* src = (const float4*)(values + (size_t)idx * V_DIM);
    float4*       dst = (float4*)(out_rv + (size_t)slot * V_DIM);
    dst[threadIdx.x] = src[threadIdx.x];  // 64 threads x float4 = 256 floats
}

// ---------------------------------------------------------------------------
// Launch
// Inputs: 0=query (2048x256), 1=W (256x256), 2=b (256), 3=keys (50000x256),
//         4=values (50000x256), 5=usage (50000), 6=top_k (scalar, ignored=8)
// Output: [retrieved_values | scores | usage_new] float32
// ---------------------------------------------------------------------------
extern "C" void kernel_launch(void* const* d_in, const int* in_sizes, int n_in,
                              void* d_out, int out_size)
{
    const float* query  = (const float*)d_in[0];
    const float* W      = (const float*)d_in[1];
    const float* bias   = (const float*)d_in[2];
    const float* keys   = (const float*)d_in[3];
    const float* values = (const float*)d_in[4];
    const float* usage  = (const float*)d_in[5];

    float* out       = (float*)d_out;
    float* out_rv    = out;                                   // 2048*8*256
    float* out_sc    = out + (size_t)B_ROWS * TOPK * V_DIM;   // 2048*8
    float* out_usage = out_sc + (size_t)B_ROWS * TOPK;        // 50000

    float* q    = nullptr; cudaGetSymbolAddress((void**)&q,    g_q);
    float* kn   = nullptr; cudaGetSymbolAddress((void**)&kn,   g_kn);
    float* sim  = nullptr; cudaGetSymbolAddress((void**)&sim,  g_sim);
    int*   topi = nullptr; cudaGetSymbolAddress((void**)&topi, g_topi);

    // 1) q = query @ W^T + b     (M=2048, N=256, K=256)
    gemm_nt_kernel<<<dim3(D_DIM / BN, B_ROWS / BM), 256>>>(
        query, W, q, bias, D_DIM, D_DIM, D_DIM);

    // 2) q_norm = q / max(||q||, eps)  (in place, IEEE div)
    l2norm_rows_kernel<<<B_ROWS / 8, 256>>>(q, q, B_ROWS);

    // 3) k_norm = keys / max(||k||, eps)  (materialized, IEEE div)
    l2norm_rows_kernel<<<(N_KEYS + 7) / 8, 256>>>(keys, kn, N_KEYS);

    // 4) sim = q_norm @ k_norm^T     (M=2048, N=50000 padded to 50048)
    gemm_nt_kernel<<<dim3(N_PAD / BN, B_ROWS / BM), 256>>>(
        q, kn, sim, nullptr, N_KEYS, D_DIM, N_PAD);

    // 5) top-8 per row -> scores (direct to output) + indices
    topk_kernel<<<B_ROWS, 256>>>(sim, out_sc, topi);

    // 6) usage passthrough, then gather + usage increments
    usage_init_kernel<<<(N_KEYS + 255) / 256, 256>>>(usage, out_usage);
    gather_kernel<<<B_ROWS * TOPK, 64>>>(values, topi, out_rv, out_usage);
}

// round 4
// speedup vs baseline: 1.0367x; 1.0344x over previous
#include <cuda_runtime.h>
#include <math.h>
#include <float.h>
#include <stdint.h>

// Problem dims (fixed by the dataset)
#define B_ROWS 2048
#define N_KEYS 50000
#define D_DIM  256
#define V_DIM  256
#define TOPK   8
#define N_PAD  50048   // 391 * 128, padded key count for GEMM grid

// ---------------------------------------------------------------------------
// Scratch (static __device__ arrays; allocation inside kernel_launch is banned)
// ---------------------------------------------------------------------------
__device__ float g_q[B_ROWS * D_DIM];                   // q = query @ W^T + b -> q_norm (in place)
__device__ float g_kn[(size_t)N_PAD * D_DIM];           // k_norm, padded to N_PAD rows (pad rows unread garbage)
__device__ float g_sim[(size_t)B_ROWS * N_PAD];         // similarity matrix scratch (~410 MB)
__device__ int   g_topi[B_ROWS * TOPK];                 // top-k indices

// ---------------------------------------------------------------------------
// Packed fp32x2 helpers (each lane is an exact IEEE fma.rn -> bitwise
// identical numerics to the scalar fmaf chain).
// ---------------------------------------------------------------------------
__device__ __forceinline__ unsigned long long pack2(float x, float y)
{
    unsigned long long r;
    asm("mov.b64 %0, {%1, %2};" : "=l"(r) : "f"(x), "f"(y));
    return r;
}
__device__ __forceinline__ void unpack2(unsigned long long v, float& x, float& y)
{
    asm("mov.b64 {%0, %1}, %2;" : "=f"(x), "=f"(y) : "l"(v));
}
__device__ __forceinline__ void ffma2(unsigned long long& d,
                                      unsigned long long a, unsigned long long b)
{
    asm("fma.rn.f32x2 %0, %1, %2, %0;" : "+l"(d) : "l"(a), "l"(b));
}

// ---------------------------------------------------------------------------
// NT SGEMM, double-buffered: C[m,n] = sum_k A[m,k]*B[n,k] (+bias[n] if bias)
// A: M x K row-major, B: (>= gridDim.x*128) x K row-major (no row guard!).
// BM=BN=128, BK=16, 256 thr, 8x8 per-thread tile as 8x4 packed f32x2 accs.
// Serial ascending-k accumulation per (m,n) -> mirrors reference numerics.
// ---------------------------------------------------------------------------
#define BM 128
#define BN 128
#define BK 16

__global__ void __launch_bounds__(256, 2) gemm_nt_kernel(
    const float* __restrict__ A, const float* __restrict__ B,
    float* __restrict__ C, const float* __restrict__ bias,
    int N, int K, int ldc)
{
    __shared__ float As[2][BK][BM];
    __shared__ float Bs[2][BK][BN];

    const int tid = threadIdx.x;
    const int tx  = tid & 15;         // 0..15 -> n
    const int ty  = tid >> 4;         // 0..15 -> m
    const int m0  = blockIdx.y * BM;
    const int n0  = blockIdx.x * BN;

    const int lr = tid >> 2;          // 0..63  tile row for loads
    const int lc = (tid & 3) * 4;     // 0,4,8,12 (k offset, float4)

    const float* Aload = A + ((size_t)m0 + lr) * K + lc;   // rows lr, lr+64
    const float* Bload = B + ((size_t)n0 + lr) * K + lc;

    unsigned long long acc2[8][4];
#pragma unroll
    for (int i = 0; i < 8; ++i)
#pragma unroll
        for (int j = 0; j < 4; ++j) acc2[i][j] = 0ull;

    // Prologue: load tile 0 into buffer 0
    float4 pa[2], pb[2];
#pragma unroll
    for (int h = 0; h < 2; ++h) {
        pa[h] = *(const float4*)(Aload + (size_t)h * 64 * K);
        pb[h] = *(const float4*)(Bload + (size_t)h * 64 * K);
    }
#pragma unroll
    for (int h = 0; h < 2; ++h) {
        int r = lr + h * 64;
        As[0][lc + 0][r] = pa[h].x; As[0][lc + 1][r] = pa[h].y;
        As[0][lc + 2][r] = pa[h].z; As[0][lc + 3][r] = pa[h].w;
        Bs[0][lc + 0][r] = pb[h].x; Bs[0][lc + 1][r] = pb[h].y;
        Bs[0][lc + 2][r] = pb[h].z; Bs[0][lc + 3][r] = pb[h].w;
    }
    __syncthreads();

    const int nt = K / BK;            // 16 tiles
    for (int t = 0; t < nt; ++t) {
        const int buf = t & 1;

        // Prefetch next tile's global data (issued before compute; latency
        // hidden under the 16-kk FMA section).
        if (t + 1 < nt) {
            int ko = (t + 1) * BK;
#pragma unroll
            for (int h = 0; h < 2; ++h) {
                pa[h] = *(const float4*)(Aload + (size_t)h * 64 * K + ko);
                pb[h] = *(const float4*)(Bload + (size_t)h * 64 * K + ko);
            }
        }

        // Compute on current buffer
#pragma unroll
        for (int kk = 0; kk < BK; ++kk) {
            float ra[8];
            *(float4*)&ra[0] = *(const float4*)&As[buf][kk][ty * 8];
            *(float4*)&ra[4] = *(const float4*)&As[buf][kk][ty * 8 + 4];
            const ulonglong2* bp = (const ulonglong2*)&Bs[buf][kk][tx * 8];
            ulonglong2 b01 = bp[0];
            ulonglong2 b23 = bp[1];
            unsigned long long rb2[4] = { b01.x, b01.y, b23.x, b23.y };

            unsigned long long ra2[8];
#pragma unroll
            for (int i = 0; i < 8; ++i) ra2[i] = pack2(ra[i], ra[i]);

#pragma unroll
            for (int i = 0; i < 8; ++i)
#pragma unroll
                for (int j = 0; j < 4; ++j)
                    ffma2(acc2[i][j], ra2[i], rb2[j]);
        }

        // Stage next tile into the other buffer
        if (t + 1 < nt) {
            const int nb = buf ^ 1;
#pragma unroll
            for (int h = 0; h < 2; ++h) {
                int r = lr + h * 64;
                As[nb][lc + 0][r] = pa[h].x; As[nb][lc + 1][r] = pa[h].y;
                As[nb][lc + 2][r] = pa[h].z; As[nb][lc + 3][r] = pa[h].w;
                Bs[nb][lc + 0][r] = pb[h].x; Bs[nb][lc + 1][r] = pb[h].y;
                Bs[nb][lc + 2][r] = pb[h].z; Bs[nb][lc + 3][r] = pb[h].w;
            }
        }
        __syncthreads();
    }

    // Epilogue: optional bias, vectorized stores
    float bi[8];
#pragma unroll
    for (int j = 0; j < 8; ++j) {
        int n = n0 + tx * 8 + j;
        bi[j] = bias ? ((n < N) ? bias[n] : 0.f) : 0.f;
    }
#pragma unroll
    for (int i = 0; i < 8; ++i) {
        int m = m0 + ty * 8 + i;
        float* crow = C + (size_t)m * ldc + n0 + tx * 8;
#pragma unroll
        for (int jv = 0; jv < 2; ++jv) {
            float a0, a1, a2, a3;
            unpack2(acc2[i][jv * 2 + 0], a0, a1);
            unpack2(acc2[i][jv * 2 + 1], a2, a3);
            float4 w;
            w.x = a0 + bi[jv * 4 + 0];
            w.y = a1 + bi[jv * 4 + 1];
            w.z = a2 + bi[jv * 4 + 2];
            w.w = a3 + bi[jv * 4 + 3];
            *(float4*)(crow + jv * 4) = w;
        }
    }
}

// ---------------------------------------------------------------------------
// Row L2-normalize: dst = src / max(||src||_2, 1e-12), IEEE div + sqrt to
// match the reference's elementwise rounding. One warp per row, D=256.
// src may equal dst.
// ---------------------------------------------------------------------------
__global__ void l2norm_rows_kernel(const float* __restrict__ src,
                                   float* __restrict__ dst, int rows)
{
    int row  = blockIdx.x * 8 + (threadIdx.x >> 5);
    int lane = threadIdx.x & 31;
    if (row >= rows) return;
    const float4* p = (const float4*)(src + (size_t)row * D_DIM);
    float4 v0 = p[lane];
    float4 v1 = p[lane + 32];
    float ss = v0.x * v0.x + v0.y * v0.y + v0.z * v0.z + v0.w * v0.w
             + v1.x * v1.x + v1.y * v1.y + v1.z * v1.z + v1.w * v1.w;
#pragma unroll
    for (int off = 16; off > 0; off >>= 1)
        ss += __shfl_xor_sync(0xffffffffu, ss, off);
    float den = fmaxf(__fsqrt_rn(ss), 1e-12f);
    v0.x = __fdiv_rn(v0.x, den); v0.y = __fdiv_rn(v0.y, den);
    v0.z = __fdiv_rn(v0.z, den); v0.w = __fdiv_rn(v0.w, den);
    v1.x = __fdiv_rn(v1.x, den); v1.y = __fdiv_rn(v1.y, den);
    v1.z = __fdiv_rn(v1.z, den); v1.w = __fdiv_rn(v1.w, den);
    float4* q = (float4*)(dst + (size_t)row * D_DIM);
    q[lane]      = v0;
    q[lane + 32] = v1;
}

// ---------------------------------------------------------------------------
// Per-row top-8. One block (256 threads) per query row. Descending scores,
// ties broken by smaller index (matches jax.lax.top_k stability).
// ---------------------------------------------------------------------------
__device__ __forceinline__ bool tk_better(float s1, int i1, float s2, int i2)
{
    return (s1 > s2) || (s1 == s2 && i1 < i2);
}

__global__ void __launch_bounds__(256) topk_kernel(
    const float* __restrict__ sim, float* __restrict__ out_scores, int* __restrict__ topi)
{
    __shared__ float ss[256 * TOPK];
    __shared__ int   si[256 * TOPK];
    __shared__ float rs[256];
    __shared__ int   rk[256];
    __shared__ int   rp[256];

    const int r   = blockIdx.x;
    const int tid = threadIdx.x;
    const float* row = sim + (size_t)r * N_PAD;

    float ls[TOPK]; int li[TOPK];
#pragma unroll
    for (int j = 0; j < TOPK; ++j) { ls[j] = -FLT_MAX; li[j] = 0x7fffffff; }

    for (int n = tid; n < N_KEYS; n += 256) {
        float s = row[n];
        if (tk_better(s, n, ls[TOPK - 1], li[TOPK - 1])) {
            ls[TOPK - 1] = s; li[TOPK - 1] = n;
#pragma unroll
            for (int q = TOPK - 1; q > 0; --q) {
                if (tk_better(ls[q], li[q], ls[q - 1], li[q - 1])) {
                    float tf = ls[q]; ls[q] = ls[q - 1]; ls[q - 1] = tf;
                    int   ti = li[q]; li[q] = li[q - 1]; li[q - 1] = ti;
                }
            }
        }
    }
#pragma unroll
    for (int j = 0; j < TOPK; ++j) { ss[tid * TOPK + j] = ls[j]; si[tid * TOPK + j] = li[j]; }
    __syncthreads();

    for (int it = 0; it < TOPK; ++it) {
        float bs = -FLT_MAX; int bk = 0x7fffffff; int bp = -1;
#pragma unroll
        for (int j = 0; j < TOPK; ++j) {
            int p = tid * TOPK + j;
            if (tk_better(ss[p], si[p], bs, bk)) { bs = ss[p]; bk = si[p]; bp = p; }
        }
        rs[tid] = bs; rk[tid] = bk; rp[tid] = bp;
        __syncthreads();
        for (int off = 128; off > 0; off >>= 1) {
            if (tid < off) {
                if (tk_better(rs[tid + off], rk[tid + off], rs[tid], rk[tid])) {
                    rs[tid] = rs[tid + off]; rk[tid] = rk[tid + off]; rp[tid] = rp[tid + off];
                }
            }
            __syncthreads();
        }
        if (tid == 0) {
            out_scores[r * TOPK + it] = rs[0];
            topi[r * TOPK + it]       = rk[0];
            ss[rp[0]] = -FLT_MAX;       // remove winner
        }
        __syncthreads();
    }
}

// ---------------------------------------------------------------------------
// usage passthrough, then gather + usage increment
// ---------------------------------------------------------------------------
__global__ void usage_init_kernel(const float* __restrict__ usage, float* __restrict__ out_usage)
{
    int i = blockIdx.x * blockDim.x + threadIdx.x;
    if (i < N_KEYS) out_usage[i] = usage[i];
}

__global__ void gather_kernel(const float* __restrict__ values, const int* __restrict__ topi,
                              float* __restrict__ out_rv, float* __restrict__ out_usage)
{
    int slot = blockIdx.x;                // 0 .. B_ROWS*TOPK-1
    int idx  = topi[slot];
    if (threadIdx.x == 0) atomicAdd(&out_usage[idx], 1.0f);
    const float4* src = (const float4*)(values + (size_t)idx * V_DIM);
    float4*       dst = (float4*)(out_rv + (size_t)slot * V_DIM);
    dst[threadIdx.x] = src[threadIdx.x];  // 64 threads x float4 = 256 floats
}

// ---------------------------------------------------------------------------
// Launch
// Inputs: 0=query (2048x256), 1=W (256x256), 2=b (256), 3=keys (50000x256),
//         4=values (50000x256), 5=usage (50000), 6=top_k (scalar, ignored=8)
// Output: [retrieved_values | scores | usage_new] float32
// ---------------------------------------------------------------------------
extern "C" void kernel_launch(void* const* d_in, const int* in_sizes, int n_in,
                              void* d_out, int out_size)
{
    const float* query  = (const float*)d_in[0];
    const float* W      = (const float*)d_in[1];
    const float* bias   = (const float*)d_in[2];
    const float* keys   = (const float*)d_in[3];
    const float* values = (const float*)d_in[4];
    const float* usage  = (const float*)d_in[5];

    float* out       = (float*)d_out;
    float* out_rv    = out;                                   // 2048*8*256
    float* out_sc    = out + (size_t)B_ROWS * TOPK * V_DIM;   // 2048*8
    float* out_usage = out_sc + (size_t)B_ROWS * TOPK;        // 50000

    float* q    = nullptr; cudaGetSymbolAddress((void**)&q,    g_q);
    float* kn   = nullptr; cudaGetSymbolAddress((void**)&kn,   g_kn);
    float* sim  = nullptr; cudaGetSymbolAddress((void**)&sim,  g_sim);
    int*   topi = nullptr; cudaGetSymbolAddress((void**)&topi, g_topi);

    // 1) q = query @ W^T + b     (M=2048, N=256, K=256)
    gemm_nt_kernel<<<dim3(D_DIM / BN, B_ROWS / BM), 256>>>(
        query, W, q, bias, D_DIM, D_DIM, D_DIM);

    // 2) q_norm = q / max(||q||, eps)  (in place, IEEE div)
    l2norm_rows_kernel<<<B_ROWS / 8, 256>>>(q, q, B_ROWS);

    // 3) k_norm = keys / max(||k||, eps)  (materialized, IEEE div)
    l2norm_rows_kernel<<<(N_KEYS + 7) / 8, 256>>>(keys, kn, N_KEYS);

    // 4) sim = q_norm @ k_norm^T     (M=2048, N=50000 padded to 50048;
    //    padded kn rows are garbage -> padded sim cols garbage, never read)
    gemm_nt_kernel<<<dim3(N_PAD / BN, B_ROWS / BM), 256>>>(
        q, kn, sim, nullptr, N_KEYS, D_DIM, N_PAD);

    // 5) top-8 per row -> scores (direct to output) + indices
    topk_kernel<<<B_ROWS, 256>>>(sim, out_sc, topi);

    // 6) usage passthrough, then gather + usage increments
    usage_init_kernel<<<(N_KEYS + 255) / 256, 256>>>(usage, out_usage);
    gather_kernel<<<B_ROWS * TOPK, 64>>>(values, topi, out_rv, out_usage);
}

// round 6
// speedup vs baseline: 1.3280x; 1.2810x over previous
#include <cuda_runtime.h>
#include <cuda_bf16.h>
#include <math.h>
#include <float.h>
#include <stdint.h>

// Problem dims (fixed by the dataset)
#define B_ROWS 2048
#define N_KEYS 50000
#define D_DIM  256
#define V_DIM  256
#define TOPK   8
#define NCAND  16
#define N_PAD  50048   // 391 * 128

// ---------------------------------------------------------------------------
// Scratch (static __device__ arrays; allocation is banned)
// ---------------------------------------------------------------------------
__device__ float          g_q[B_ROWS * D_DIM];               // q_norm
__device__ float          g_kn[(size_t)N_KEYS * D_DIM];      // k_norm
__device__ __nv_bfloat16  g_ah[(size_t)B_ROWS * D_DIM];      // bf16(q_norm)
__device__ __nv_bfloat16  g_bh[(size_t)N_PAD * D_DIM];       // bf16(k_norm), pad rows zero
__device__ float          g_sim[(size_t)B_ROWS * N_PAD];     // approx sims (~410 MB)
__device__ int            g_cand[B_ROWS * NCAND];
__device__ int            g_topi[B_ROWS * TOPK];

// ---------------------------------------------------------------------------
// bf16 mma.sync candidate GEMM: sim[m][n] = sum_k Ah[m][k] * Bh[n][k]
// CTA tile 128x128, 8 warps (2x4), warp tile 64x32, BK=32, double-buffered.
// Smem row stride 40 bf16 (80 B): 16B-aligned vector stores, conflict-free
// fragment loads (80 B = 20 banks; 8 rows land on distinct bank groups).
// ---------------------------------------------------------------------------
#define KST 40   // smem row stride in bf16 elements

__global__ void __launch_bounds__(256) simtc_kernel(
    const __nv_bfloat16* __restrict__ Ah,
    const __nv_bfloat16* __restrict__ Bh,
    float* __restrict__ sim)
{
    __shared__ uint16_t As[2][128][KST];
    __shared__ uint16_t Bs[2][128][KST];

    const int tid  = threadIdx.x;
    const int wid  = tid >> 5;
    const int lane = tid & 31;
    const int gid  = lane >> 2;        // 0..7
    const int q2   = (lane & 3) * 2;   // 0,2,4,6
    const int wm   = (wid >> 2) * 64;  // warp m offset: 0 or 64
    const int wn   = (wid & 3) * 32;   // warp n offset: 0,32,64,96
    const int m0   = blockIdx.y * 128;
    const int n0   = blockIdx.x * 128;

    const int lrow = tid >> 2;         // 0..63? no: 256 threads, u = tid + i*256
    (void)lrow;

    float c[4][4][4];
#pragma unroll
    for (int i = 0; i < 4; ++i)
#pragma unroll
        for (int j = 0; j < 4; ++j)
#pragma unroll
            for (int v = 0; v < 4; ++v) c[i][j][v] = 0.f;

    // chunk loader: A/B tile 128 rows x 32 bf16 (64 B = 4 x 16B units per row)
    auto load_chunk = [&](int buf, int kc) {
#pragma unroll
        for (int i = 0; i < 2; ++i) {
            int u   = tid + i * 256;   // 0..511
            int row = u >> 2;
            int cu  = u & 3;           // 16B unit
            uint4 va = *(const uint4*)(Ah + (size_t)(m0 + row) * D_DIM + kc * 32 + cu * 8);
            *(uint4*)&As[buf][row][cu * 8] = va;
            uint4 vb = *(const uint4*)(Bh + (size_t)(n0 + row) * D_DIM + kc * 32 + cu * 8);
            *(uint4*)&Bs[buf][row][cu * 8] = vb;
        }
    };

    auto compute_chunk = [&](int buf) {
#pragma unroll
        for (int ks = 0; ks < 2; ++ks) {
            const int k0 = ks * 16;
            uint32_t a[4][4];
#pragma unroll
            for (int mt = 0; mt < 4; ++mt) {
                int r0 = wm + mt * 16 + gid;
                a[mt][0] = *(const uint32_t*)&As[buf][r0    ][k0 + q2];
                a[mt][1] = *(const uint32_t*)&As[buf][r0 + 8][k0 + q2];
                a[mt][2] = *(const uint32_t*)&As[buf][r0    ][k0 + q2 + 8];
                a[mt][3] = *(const uint32_t*)&As[buf][r0 + 8][k0 + q2 + 8];
            }
            uint32_t b[4][2];
#pragma unroll
            for (int nt = 0; nt < 4; ++nt) {
                int n = wn + nt * 8 + gid;
                b[nt][0] = *(const uint32_t*)&Bs[buf][n][k0 + q2];
                b[nt][1] = *(const uint32_t*)&Bs[buf][n][k0 + q2 + 8];
            }
#pragma unroll
            for (int mt = 0; mt < 4; ++mt)
#pragma unroll
                for (int nt = 0; nt < 4; ++nt)
                    asm volatile(
                        "mma.sync.aligned.m16n8k16.row.col.f32.bf16.bf16.f32 "
                        "{%0,%1,%2,%3}, {%4,%5,%6,%7}, {%8,%9}, {%0,%1,%2,%3};"
                        : "+f"(c[mt][nt][0]), "+f"(c[mt][nt][1]),
                          "+f"(c[mt][nt][2]), "+f"(c[mt][nt][3])
                        : "r"(a[mt][0]), "r"(a[mt][1]), "r"(a[mt][2]), "r"(a[mt][3]),
                          "r"(b[nt][0]), "r"(b[nt][1]));
        }
    };

    load_chunk(0, 0);
    __syncthreads();

    const int nchunk = D_DIM / 32;     // 8
#pragma unroll
    for (int t = 0; t < nchunk; ++t) {
        if (t + 1 < nchunk) load_chunk((t + 1) & 1, t + 1);
        compute_chunk(t & 1);
        __syncthreads();
    }

    // Epilogue: write fp32 sims
#pragma unroll
    for (int mt = 0; mt < 4; ++mt) {
        int r0 = m0 + wm + mt * 16 + gid;
#pragma unroll
        for (int nt = 0; nt < 4; ++nt) {
            int col = n0 + wn + nt * 8 + q2;
            *(float2*)(sim + (size_t)r0 * N_PAD + col)       = make_float2(c[mt][nt][0], c[mt][nt][1]);
            *(float2*)(sim + (size_t)(r0 + 8) * N_PAD + col) = make_float2(c[mt][nt][2], c[mt][nt][3]);
        }
    }
}

// ---------------------------------------------------------------------------
// fp32 NT SGEMM (small q = query @ W^T + b only)
// ---------------------------------------------------------------------------
#define BM 128
#define BN 128
#define BK 16

__global__ void __launch_bounds__(256) gemm_nt_kernel(
    const float* __restrict__ A, const float* __restrict__ B,
    float* __restrict__ C, const float* __restrict__ bias,
    int N, int K, int ldc)
{
    __shared__ float As[BK][BM];
    __shared__ float Bs[BK][BN];
    const int tid = threadIdx.x;
    const int tx  = tid & 15;
    const int ty  = tid >> 4;
    const int m0  = blockIdx.y * BM;
    const int n0  = blockIdx.x * BN;
    const int lr  = tid >> 2;
    const int lc  = (tid & 3) * 4;
    const float* Aptr = A + (size_t)m0 * K;
    const float* Bptr = B + (size_t)n0 * K;

    float acc[8][8];
#pragma unroll
    for (int i = 0; i < 8; ++i)
#pragma unroll
        for (int j = 0; j < 8; ++j) acc[i][j] = 0.f;

    for (int k0 = 0; k0 < K; k0 += BK) {
#pragma unroll
        for (int h = 0; h < 2; ++h) {
            int r = lr + h * 64;
            float4 v = *(const float4*)(Aptr + (size_t)r * K + k0 + lc);
            As[lc + 0][r] = v.x; As[lc + 1][r] = v.y;
            As[lc + 2][r] = v.z; As[lc + 3][r] = v.w;
            float4 w = *(const float4*)(Bptr + (size_t)r * K + k0 + lc);
            Bs[lc + 0][r] = w.x; Bs[lc + 1][r] = w.y;
            Bs[lc + 2][r] = w.z; Bs[lc + 3][r] = w.w;
        }
        __syncthreads();
#pragma unroll
        for (int kk = 0; kk < BK; ++kk) {
            float ra[8], rb[8];
            *(float4*)&ra[0] = *(const float4*)&As[kk][ty * 8];
            *(float4*)&ra[4] = *(const float4*)&As[kk][ty * 8 + 4];
            *(float4*)&rb[0] = *(const float4*)&Bs[kk][tx * 8];
            *(float4*)&rb[4] = *(const float4*)&Bs[kk][tx * 8 + 4];
#pragma unroll
            for (int i = 0; i < 8; ++i)
#pragma unroll
                for (int j = 0; j < 8; ++j)
                    acc[i][j] = fmaf(ra[i], rb[j], acc[i][j]);
        }
        __syncthreads();
    }
    float bi[8];
#pragma unroll
    for (int j = 0; j < 8; ++j) {
        int n = n0 + tx * 8 + j;
        bi[j] = bias ? ((n < N) ? bias[n] : 0.f) : 0.f;
    }
#pragma unroll
    for (int i = 0; i < 8; ++i) {
        int m = m0 + ty * 8 + i;
        float* crow = C + (size_t)m * ldc + n0 + tx * 8;
#pragma unroll
        for (int jv = 0; jv < 8; jv += 4) {
            float4 w;
            w.x = acc[i][jv + 0] + bi[jv + 0];
            w.y = acc[i][jv + 1] + bi[jv + 1];
            w.z = acc[i][jv + 2] + bi[jv + 2];
            w.w = acc[i][jv + 3] + bi[jv + 3];
            *(float4*)(crow + jv) = w;
        }
    }
}

// ---------------------------------------------------------------------------
// Row L2-normalize (IEEE div/sqrt to match reference elementwise rounding)
// ---------------------------------------------------------------------------
__global__ void l2norm_rows_kernel(const float* __restrict__ src,
                                   float* __restrict__ dst, int rows)
{
    int row  = blockIdx.x * 8 + (threadIdx.x >> 5);
    int lane = threadIdx.x & 31;
    if (row >= rows) return;
    const float4* p = (const float4*)(src + (size_t)row * D_DIM);
    float4 v0 = p[lane];
    float4 v1 = p[lane + 32];
    float ss = v0.x * v0.x + v0.y * v0.y + v0.z * v0.z + v0.w * v0.w
             + v1.x * v1.x + v1.y * v1.y + v1.z * v1.z + v1.w * v1.w;
#pragma unroll
    for (int off = 16; off > 0; off >>= 1)
        ss += __shfl_xor_sync(0xffffffffu, ss, off);
    float den = fmaxf(__fsqrt_rn(ss), 1e-12f);
    v0.x = __fdiv_rn(v0.x, den); v0.y = __fdiv_rn(v0.y, den);
    v0.z = __fdiv_rn(v0.z, den); v0.w = __fdiv_rn(v0.w, den);
    v1.x = __fdiv_rn(v1.x, den); v1.y = __fdiv_rn(v1.y, den);
    v1.z = __fdiv_rn(v1.z, den); v1.w = __fdiv_rn(v1.w, den);
    float4* q = (float4*)(dst + (size_t)row * D_DIM);
    q[lane]      = v0;
    q[lane + 32] = v1;
}

// ---------------------------------------------------------------------------
// bf16 cast (rows >= rows_src get zeros, covering the N_PAD padding)
// ---------------------------------------------------------------------------
__global__ void prep_bf16_kernel(const float* __restrict__ src,
                                 __nv_bfloat16* __restrict__ dst,
                                 int rows_src, int rows_total)
{
    int i = blockIdx.x * blockDim.x + threadIdx.x;
    if (i >= rows_total * D_DIM) return;
    int r = i >> 8;
    dst[i] = (r < rows_src) ? __float2bfloat16(src[i]) : __float2bfloat16(0.f);
}

// ---------------------------------------------------------------------------
// Per-row top-16 candidates from approx sims (set only). 128 thr/row.
// ---------------------------------------------------------------------------
__device__ __forceinline__ bool tk_better(float s1, int i1, float s2, int i2)
{
    return (s1 > s2) || (s1 == s2 && i1 < i2);
}

__global__ void __launch_bounds__(128) topk16_kernel(
    const float* __restrict__ sim, int* __restrict__ cand)
{
    __shared__ float ss[128 * NCAND];
    __shared__ int   si[128 * NCAND];
    __shared__ float rs[128];
    __shared__ int   rk[128];
    __shared__ int   rp[128];

    const int r   = blockIdx.x;
    const int tid = threadIdx.x;
    const float* row = sim + (size_t)r * N_PAD;

    float ls[NCAND]; int li[NCAND];
#pragma unroll
    for (int j = 0; j < NCAND; ++j) { ls[j] = -FLT_MAX; li[j] = 0x7fffffff; }

    for (int n = tid; n < N_KEYS; n += 128) {
        float s = row[n];
        if (tk_better(s, n, ls[NCAND - 1], li[NCAND - 1])) {
            ls[NCAND - 1] = s; li[NCAND - 1] = n;
#pragma unroll
            for (int q = NCAND - 1; q > 0; --q) {
                if (tk_better(ls[q], li[q], ls[q - 1], li[q - 1])) {
                    float tf = ls[q]; ls[q] = ls[q - 1]; ls[q - 1] = tf;
                    int   ti = li[q]; li[q] = li[q - 1]; li[q - 1] = ti;
                }
            }
        }
    }
#pragma unroll
    for (int j = 0; j < NCAND; ++j) { ss[tid * NCAND + j] = ls[j]; si[tid * NCAND + j] = li[j]; }
    __syncthreads();

    for (int it = 0; it < NCAND; ++it) {
        float bs = -FLT_MAX; int bk = 0x7fffffff; int bp = -1;
#pragma unroll
        for (int j = 0; j < NCAND; ++j) {
            int p = tid * NCAND + j;
            if (tk_better(ss[p], si[p], bs, bk)) { bs = ss[p]; bk = si[p]; bp = p; }
        }
        rs[tid] = bs; rk[tid] = bk; rp[tid] = bp;
        __syncthreads();
        for (int off = 64; off > 0; off >>= 1) {
            if (tid < off) {
                if (tk_better(rs[tid + off], rk[tid + off], rs[tid], rk[tid])) {
                    rs[tid] = rs[tid + off]; rk[tid] = rk[tid + off]; rp[tid] = rp[tid + off];
                }
            }
            __syncthreads();
        }
        if (tid == 0) {
            cand[r * NCAND + it] = rk[0];
            ss[rp[0]] = -FLT_MAX;
        }
        __syncthreads();
    }
}

// ---------------------------------------------------------------------------
// Exact rescore: one warp per row; lane c rescores candidate c with the
// serial ascending-k fp32 fma chain (identical numerics to the R2-R4 GEMM).
// ---------------------------------------------------------------------------
__global__ void __launch_bounds__(256) rescore_kernel(
    const float* __restrict__ q, const float* __restrict__ kn,
    const int* __restrict__ cand,
    float* __restrict__ out_scores, int* __restrict__ topi)
{
    int gw   = (blockIdx.x * blockDim.x + threadIdx.x) >> 5;   // row
    int lane = threadIdx.x & 31;
    if (gw >= B_ROWS) return;

    float s  = -FLT_MAX;
    int   ix = 0x7fffffff;
    if (lane < NCAND) {
        ix = cand[gw * NCAND + lane];
        const float* qr = q  + (size_t)gw * D_DIM;
        const float* kr = kn + (size_t)ix * D_DIM;
        float acc = 0.f;
#pragma unroll 8
        for (int k = 0; k < D_DIM; ++k)
            acc = fmaf(qr[k], kr[k], acc);
        s = acc;
    }
    int rank = 0;
#pragma unroll
    for (int j = 0; j < NCAND; ++j) {
        float sj = __shfl_sync(0xffffffffu, s, j);
        int   ij = __shfl_sync(0xffffffffu, ix, j);
        if (j != lane && tk_better(sj, ij, s, ix)) ++rank;
    }
    if (lane < NCAND && rank < TOPK) {
        out_scores[gw * TOPK + rank] = s;
        topi[gw * TOPK + rank]       = ix;
    }
}

// ---------------------------------------------------------------------------
// usage passthrough + gather
// ---------------------------------------------------------------------------
__global__ void usage_init_kernel(const float* __restrict__ usage, float* __restrict__ out_usage)
{
    int i = blockIdx.x * blockDim.x + threadIdx.x;
    if (i < N_KEYS) out_usage[i] = usage[i];
}

__global__ void gather_kernel(const float* __restrict__ values, const int* __restrict__ topi,
                              float* __restrict__ out_rv, float* __restrict__ out_usage)
{
    int slot = blockIdx.x;
    int idx  = topi[slot];
    if (threadIdx.x == 0) atomicAdd(&out_usage[idx], 1.0f);
    const float4* src = (const float4*)(values + (size_t)idx * V_DIM);
    float4*       dst = (float4*)(out_rv + (size_t)slot * V_DIM);
    dst[threadIdx.x] = src[threadIdx.x];
}

// ---------------------------------------------------------------------------
// Launch
// ---------------------------------------------------------------------------
extern "C" void kernel_launch(void* const* d_in, const int* in_sizes, int n_in,
                              void* d_out, int out_size)
{
    const float* query  = (const float*)d_in[0];
    const float* W      = (const float*)d_in[1];
    const float* bias   = (const float*)d_in[2];
    const float* keys   = (const float*)d_in[3];
    const float* values = (const float*)d_in[4];
    const float* usage  = (const float*)d_in[5];

    float* out       = (float*)d_out;
    float* out_rv    = out;
    float* out_sc    = out + (size_t)B_ROWS * TOPK * V_DIM;
    float* out_usage = out_sc + (size_t)B_ROWS * TOPK;

    float*         q    = nullptr; cudaGetSymbolAddress((void**)&q,    g_q);
    float*         kn   = nullptr; cudaGetSymbolAddress((void**)&kn,   g_kn);
    __nv_bfloat16* ah   = nullptr; cudaGetSymbolAddress((void**)&ah,   g_ah);
    __nv_bfloat16* bh   = nullptr; cudaGetSymbolAddress((void**)&bh,   g_bh);
    float*         sim  = nullptr; cudaGetSymbolAddress((void**)&sim,  g_sim);
    int*           cand = nullptr; cudaGetSymbolAddress((void**)&cand, g_cand);
    int*           topi = nullptr; cudaGetSymbolAddress((void**)&topi, g_topi);

    // 1) q = query @ W^T + b
    gemm_nt_kernel<<<dim3(D_DIM / BN, B_ROWS / BM), 256>>>(
        query, W, q, bias, D_DIM, D_DIM, D_DIM);

    // 2) normalize (IEEE elementwise, matches reference)
    l2norm_rows_kernel<<<B_ROWS / 8, 256>>>(q, q, B_ROWS);
    l2norm_rows_kernel<<<(N_KEYS + 7) / 8, 256>>>(keys, kn, N_KEYS);

    // 3) bf16 casts (pad rows of bh zeroed)
    prep_bf16_kernel<<<(B_ROWS * D_DIM + 255) / 256, 256>>>(q, ah, B_ROWS, B_ROWS);
    prep_bf16_kernel<<<(N_PAD * D_DIM + 255) / 256, 256>>>(kn, bh, N_KEYS, N_PAD);

    // 4) bf16 tensor-core approx sim (error ~1e-4 << candidate margin)
    simtc_kernel<<<dim3(N_PAD / 128, B_ROWS / 128), 256>>>(ah, bh, sim);

    // 5) top-16 candidate sets
    topk16_kernel<<<B_ROWS, 128>>>(sim, cand);

    // 6) exact fp32 rescore -> top-8 scores + indices
    rescore_kernel<<<(B_ROWS * 32 + 255) / 256, 256>>>(q, kn, cand, out_sc, topi);

    // 7) usage + gather
    usage_init_kernel<<<(N_KEYS + 255) / 256, 256>>>(usage, out_usage);
    gather_kernel<<<B_ROWS * TOPK, 64>>>(values, topi, out_rv, out_usage);
}